// round 17
// baseline (speedup 1.0000x reference)
#include <cuda_runtime.h>
#include <cuda_bf16.h>

#define BATCH 256
#define L 256
#define D 64
#define NST 24
#define CPROJ 72

typedef unsigned long long u64;

// ---------------- scratch ----------------------------------------------------
__device__ float g_xt[BATCH * L * D];
__device__ float g_dtr[BATCH * 4 * NST * L];
__device__ float g_bc[BATCH * 4 * 48 * L];
__device__ float g_ysum[BATCH * L * D];

__device__ __forceinline__ int map_l(int k, int l) {
    int lm = (k & 2) ? (255 - l) : l;
    if (k & 1) lm = ((lm & 15) << 4) | (lm >> 4);
    return lm;
}
__device__ __forceinline__ float silu(float x) { return x / (1.f + __expf(-x)); }

__device__ __forceinline__ u64 pk2(float lo, float hi) {
    u64 r; asm("mov.b64 %0,{%1,%2};" : "=l"(r) : "f"(lo), "f"(hi)); return r;
}
__device__ __forceinline__ void unpk2(float& lo, float& hi, u64 v) {
    asm("mov.b64 {%0,%1},%2;" : "=f"(lo), "=f"(hi) : "l"(v));
}
__device__ __forceinline__ u64 mul2(u64 a, u64 b) {
    u64 r; asm("mul.rn.f32x2 %0,%1,%2;" : "=l"(r) : "l"(a), "l"(b)); return r;
}
__device__ __forceinline__ u64 fma2(u64 a, u64 b, u64 c) {
    u64 r; asm("fma.rn.f32x2 %0,%1,%2,%3;" : "=l"(r) : "l"(a), "l"(b), "l"(c)); return r;
}
__device__ __forceinline__ unsigned f2tf(float f) {
    unsigned u; asm("cvt.rna.tf32.f32 %0,%1;" : "=r"(u) : "f"(f)); return u;
}
__device__ __forceinline__ void mma_tf32(float c[4],
                                         unsigned a0, unsigned a1, unsigned a2, unsigned a3,
                                         unsigned b0, unsigned b1) {
    asm volatile(
        "mma.sync.aligned.m16n8k8.row.col.f32.tf32.tf32.f32 "
        "{%0,%1,%2,%3},{%4,%5,%6,%7},{%8,%9},{%0,%1,%2,%3};"
        : "+f"(c[0]), "+f"(c[1]), "+f"(c[2]), "+f"(c[3])
        : "r"(a0), "r"(a1), "r"(a2), "r"(a3), "r"(b0), "r"(b1));
}

// ---------------- K1: fused rearrange + dwconv + silu + patch + BN ------------
#define FRONT_SMEM ((64 * 65 + 4 * 64 * 68 + 66 * 68) * 4)
__global__ void __launch_bounds__(512) k_front(const float* __restrict__ xin,
                                               const float* __restrict__ cw,
                                               const float* __restrict__ cb,
                                               const float* __restrict__ pw,
                                               const float* __restrict__ pb,
                                               const float* __restrict__ gam,
                                               const float* __restrict__ bet,
                                               const float* __restrict__ mn,
                                               const float* __restrict__ vr,
                                               float* __restrict__ xt,
                                               float* __restrict__ ysum) {
    extern __shared__ float fsm[];
    float* ws  = fsm;
    float* xcs = fsm + 64 * 65;
    float* ts  = xcs + 4 * 64 * 68;
    int b = blockIdx.x;
    int t = threadIdx.x;

    {
        float4* yz = (float4*)(ysum + b * 16384);
        float4 z4 = make_float4(0.f, 0.f, 0.f, 0.f);
#pragma unroll
        for (int i = 0; i < 8; i++) yz[t + i * 512] = z4;
    }
    for (int i = t; i < 4096; i += 512) ws[(i & 63) * 65 + (i >> 6)] = pw[i];

    const float* xbb = xin + b * 16384;
#pragma unroll 1
    for (int c = 0; c < 4; c++) {
        __syncthreads();
        for (int i = t; i < 66 * 68; i += 512) ts[i] = 0.f;
        __syncthreads();
        const float* xb = xbb + c * 16;
#pragma unroll
        for (int it = 0; it < 8; it++) {
            int e = it * 512 + t;
            int pq = e >> 4, ij = e & 15;
            int p = pq >> 4, q = pq & 15;
            int i2 = ij >> 2, j2 = ij & 3;
            ts[(1 + p * 4 + i2) * 68 + 1 + q * 4 + j2] = xb[pq * 64 + ij];
        }
        __syncthreads();
        float wr[9];
#pragma unroll
        for (int i = 0; i < 9; i++) wr[i] = __ldg(&cw[c * 9 + i]);
        float cbv = __ldg(&cb[c]);
        int h = t >> 3, wq = t & 7;
        float* orow = xcs + (c * 64 + h) * 68;
#pragma unroll
        for (int j = 0; j < 8; j++) {
            int wcol = wq * 8 + j;
            float acc = cbv;
#pragma unroll
            for (int di = 0; di < 3; di++)
#pragma unroll
                for (int dj = 0; dj < 3; dj++)
                    acc += ts[(h + di) * 68 + wcol + dj] * wr[di * 3 + dj];
            orow[wcol] = silu(acc);
        }
    }
    __syncthreads();

    int e = t & 63, li = t >> 6;
    float sc = __ldg(&gam[e]) * rsqrtf(__ldg(&vr[e]) + 1e-5f);
    float pbv = __ldg(&pb[e]), mnv = __ldg(&mn[e]), btv = __ldg(&bet[e]);
#pragma unroll 1
    for (int rg = 0; rg < 4; rg++) {
        int r0 = rg * 64 + li * 8;
        int rof[8];
#pragma unroll
        for (int j = 0; j < 8; j++) {
            int row = r0 + j;
            rof[j] = ((row >> 4) * 4) * 68 + (row & 15) * 4;
        }
        float acc[8];
#pragma unroll
        for (int j = 0; j < 8; j++) acc[j] = 0.f;
#pragma unroll
        for (int m4 = 0; m4 < 16; m4++) {
            int c4 = m4 >> 2, i2m = m4 & 3;
            int boff = c4 * 4352 + i2m * 68;
            float4 xv[8];
#pragma unroll
            for (int j = 0; j < 8; j++)
                xv[j] = *(const float4*)&xcs[boff + rof[j]];
#pragma unroll
            for (int dd = 0; dd < 4; dd++) {
                float wv = ws[(m4 * 4 + dd) * 65 + e];
#pragma unroll
                for (int j = 0; j < 8; j++) {
                    float v = dd == 0 ? xv[j].x : dd == 1 ? xv[j].y : dd == 2 ? xv[j].z : xv[j].w;
                    acc[j] += v * wv;
                }
            }
        }
#pragma unroll
        for (int j = 0; j < 8; j++)
            xt[(b * 256 + r0 + j) * 64 + e] = (acc[j] + pbv - mnv) * sc + btv;
    }
}

// ---------------- K3: x_dbl projection via tf32 mma, 2 CTAs per (k,b) --------
#define AS_STRIDE 136
#define BS_STRIDE 72
__global__ void __launch_bounds__(256, 3) k_proj(const float* __restrict__ xt,
                                                 const float* __restrict__ xpw,
                                                 float* __restrict__ dtrg,
                                                 float* __restrict__ bc) {
    extern __shared__ unsigned sm[];
    unsigned* As = sm;
    unsigned* Bs = sm + 64 * AS_STRIDE;
    int kh = blockIdx.x, b = blockIdx.y;
    int k = kh & 3, half = kh >> 2;
    int t = threadIdx.x, w = t >> 5, lane = t & 31;
    int gid = lane >> 2, tig = lane & 3;
    const float* wk = xpw + k * CPROJ * 64;

    for (int i = t; i < CPROJ * 64; i += 256) {
        int c = i >> 6, kk = i & 63;
        Bs[kk * BS_STRIDE + c] = f2tf(wk[i]);
    }
    {
        int lr = t >> 1;
        int kk0 = (t & 1) * 32;
        int lm = map_l(k, half * 128 + lr);
        const float4* xp = (const float4*)(xt + (b * 256 + lm) * 64 + kk0);
#pragma unroll
        for (int j4 = 0; j4 < 8; j4++) {
            float4 v = __ldg(xp + j4);
            As[(kk0 + 4 * j4 + 0) * AS_STRIDE + lr] = f2tf(v.x);
            As[(kk0 + 4 * j4 + 1) * AS_STRIDE + lr] = f2tf(v.y);
            As[(kk0 + 4 * j4 + 2) * AS_STRIDE + lr] = f2tf(v.z);
            As[(kk0 + 4 * j4 + 3) * AS_STRIDE + lr] = f2tf(v.w);
        }
    }
    __syncthreads();

    int r0 = w * 16;
    unsigned a[8][4];
#pragma unroll
    for (int ks = 0; ks < 8; ks++) {
        int kb = ks * 8;
        a[ks][0] = As[(kb + tig) * AS_STRIDE + r0 + gid];
        a[ks][1] = As[(kb + tig) * AS_STRIDE + r0 + gid + 8];
        a[ks][2] = As[(kb + tig + 4) * AS_STRIDE + r0 + gid];
        a[ks][3] = As[(kb + tig + 4) * AS_STRIDE + r0 + gid + 8];
    }

    float* dto = dtrg + (b * 4 + k) * NST * 256;
    float* bco = bc + (b * 4 + k) * 48 * 256;
    int rg = half * 128 + r0 + gid;
#pragma unroll
    for (int n = 0; n < 9; n++) {
        float acc[4] = {0.f, 0.f, 0.f, 0.f};
#pragma unroll
        for (int ks = 0; ks < 8; ks++) {
            int kb = ks * 8;
            unsigned b0 = Bs[(kb + tig) * BS_STRIDE + n * 8 + gid];
            unsigned b1 = Bs[(kb + tig + 4) * BS_STRIDE + n * 8 + gid];
            mma_tf32(acc, a[ks][0], a[ks][1], a[ks][2], a[ks][3], b0, b1);
        }
        int c0 = n * 8 + 2 * tig;
#pragma unroll
        for (int q = 0; q < 2; q++) {
            int c = c0 + q;
            float* base = (c < 24) ? (dto + c * 256) : (bco + (c - 24) * 256);
            base[rg]     = acc[q];
            base[rg + 8] = acc[q + 2];
        }
    }
}
#define PROJ_SMEM ((64 * AS_STRIDE + 64 * BS_STRIDE) * 4)

// ---------------- K4: scan (MUFU hoisted out of the recurrence loop) ----------
__global__ void __launch_bounds__(64, 7) k_scan(const float* __restrict__ xt,
                                                const float* __restrict__ dtrg,
                                                const float* __restrict__ bc,
                                                const float* __restrict__ dtw_g,
                                                const float* __restrict__ alog,
                                                const float* __restrict__ dbias,
                                                const float* __restrict__ Dsv,
                                                float* __restrict__ ysum) {
    __shared__ __align__(16) float sbc[16][48];
    __shared__ __align__(16) float sdtr[NST * 16];
    __shared__ float su[16][64];
    int k = blockIdx.x, b = blockIdx.y;
    int d = threadIdx.x;
    int kd = k * 64 + d;

    float dtw[NST];
    {
        const float4* dwp = (const float4*)(dtw_g + kd * NST);
#pragma unroll
        for (int i = 0; i < 6; i++) {
            float4 v = __ldg(dwp + i);
            dtw[4 * i] = v.x; dtw[4 * i + 1] = v.y;
            dtw[4 * i + 2] = v.z; dtw[4 * i + 3] = v.w;
        }
    }
    float a0 = -__expf(__ldg(&alog[kd * NST]));
    bool chain = (a0 != 0.f);
#pragma unroll
    for (int n = 1; n < NST; n++) {
        float an = -__expf(__ldg(&alog[kd * NST + n]));
        chain = chain && (fabsf(an - (float)(n + 1) * a0) <= 1e-4f * fabsf(an));
    }
    float bias = __ldg(&dbias[kd]);
    float Dv = __ldg(&Dsv[kd]);
    int kb = b * 4 + k;
    const float* dtrp = dtrg + kb * NST * 256;
    const float* bcp = bc + kb * 48 * 256;
    const float* xrow = xt + b * 256 * 64;
    float* yb = ysum + b * 256 * 64;

    u64 h2[12];
#pragma unroll
    for (int p = 0; p < 12; p++) h2[p] = 0ull;

    for (int l0 = 0; l0 < 256; l0 += 16) {
        __syncthreads();
#pragma unroll
        for (int m = 0; m < 12; m++) {
            int idx = d * 12 + m;
            sbc[idx & 15][idx >> 4] = bcp[(idx >> 4) * 256 + l0 + (idx & 15)];
        }
#pragma unroll
        for (int m = 0; m < 6; m++) {
            int idx = d * 6 + m;
            sdtr[idx] = dtrp[(idx >> 4) * 256 + l0 + (idx & 15)];
        }
#pragma unroll
        for (int i = 0; i < 16; i++)
            su[i][d] = __ldg(&xrow[map_l(k, l0 + i) * 64 + d]);
        __syncthreads();

        float dtc[16];
        {
            u64 dt2[8];
#pragma unroll
            for (int ip = 0; ip < 8; ip++) dt2[ip] = 0ull;
#pragma unroll
            for (int r = 0; r < NST; r++) {
                u64 wp = pk2(dtw[r], dtw[r]);
#pragma unroll
                for (int q = 0; q < 4; q++) {
                    ulonglong2 v = *(const ulonglong2*)&sdtr[r * 16 + 4 * q];
                    dt2[2 * q]     = fma2(wp, v.x, dt2[2 * q]);
                    dt2[2 * q + 1] = fma2(wp, v.y, dt2[2 * q + 1]);
                }
            }
#pragma unroll
            for (int ip = 0; ip < 8; ip++) unpk2(dtc[2 * ip], dtc[2 * ip + 1], dt2[ip]);
        }

        if (chain) {
            // hoisted MUFU pre-pass: all 16 steps independent -> pipelines
            float qv[16], duv[16];
#pragma unroll
            for (int i = 0; i < 16; i++) {
                float xv = dtc[i] + bias;
                float delta = (xv > 15.f) ? xv : __logf(1.f + __expf(xv));
                duv[i] = delta * su[i][d];
                qv[i] = __expf(delta * a0);
            }
#pragma unroll 2
            for (int i = 0; i < 16; i++) {
                int l = l0 + i;
                float q = qv[i];
                float du = duv[i];
                float q2s = q * q, q4s = q2s * q2s, q8s = q4s * q4s, q16s = q8s * q8s;
                u64 Q2 = pk2(q2s, q2s), Q4 = pk2(q4s, q4s);
                u64 Q8 = pk2(q8s, q8s), Q16 = pk2(q16s, q16s);
                u64 P[12];
                P[0] = pk2(q, q2s);
                P[1] = mul2(P[0], Q2);
                P[2] = mul2(P[0], Q4);  P[3] = mul2(P[1], Q4);
                P[4] = mul2(P[0], Q8);  P[5] = mul2(P[1], Q8);
                P[6] = mul2(P[2], Q8);  P[7] = mul2(P[3], Q8);
                P[8] = mul2(P[0], Q16); P[9] = mul2(P[1], Q16);
                P[10] = mul2(P[2], Q16); P[11] = mul2(P[3], Q16);
                u64 du2 = pk2(du, du);
                u64 y2a = 0ull, y2b = 0ull;
#pragma unroll
                for (int qq = 0; qq < 6; qq++) {
                    ulonglong2 Bv = *(const ulonglong2*)&sbc[i][4 * qq];
                    ulonglong2 Cv = *(const ulonglong2*)&sbc[i][24 + 4 * qq];
                    int p0 = 2 * qq, p1 = 2 * qq + 1;
                    h2[p0] = fma2(P[p0], h2[p0], mul2(du2, Bv.x));
                    y2a = fma2(h2[p0], Cv.x, y2a);
                    h2[p1] = fma2(P[p1], h2[p1], mul2(du2, Bv.y));
                    y2b = fma2(h2[p1], Cv.y, y2b);
                }
                float ylo, yhi, zlo, zhi;
                unpk2(ylo, yhi, y2a); unpk2(zlo, zhi, y2b);
                atomicAdd(&yb[map_l(k, l) * 64 + d], ylo + yhi + zlo + zhi + Dv * su[i][d]);
            }
        } else {
#pragma unroll 1
            for (int i = 0; i < 16; i++) {
                int l = l0 + i;
                float xv = dtc[i] + bias;
                float delta = (xv > 15.f) ? xv : __logf(1.f + __expf(xv));
                float u = su[i][d];
                float du = delta * u;
                u64 du2 = pk2(du, du);
                u64 y2 = 0ull;
#pragma unroll
                for (int qq = 0; qq < 6; qq++) {
                    ulonglong2 Bv = *(const ulonglong2*)&sbc[i][4 * qq];
                    ulonglong2 Cv = *(const ulonglong2*)&sbc[i][24 + 4 * qq];
#pragma unroll
                    for (int s = 0; s < 2; s++) {
                        int p = 2 * qq + s;
                        float alo = -__expf(__ldg(&alog[kd * NST + 2 * p]));
                        float ahi = -__expf(__ldg(&alog[kd * NST + 2 * p + 1]));
                        u64 dA = pk2(__expf(delta * alo), __expf(delta * ahi));
                        u64 Bp = s ? Bv.y : Bv.x;
                        u64 Cp = s ? Cv.y : Cv.x;
                        h2[p] = fma2(dA, h2[p], mul2(du2, Bp));
                        y2 = fma2(h2[p], Cp, y2);
                    }
                }
                float ylo, yhi;
                unpk2(ylo, yhi, y2);
                atomicAdd(&yb[map_l(k, l) * 64 + d], ylo + yhi + Dv * u);
            }
        }
    }
}

// ---------------- K5: LN + z-gate + out_proj via tf32 mma ---------------------
#define FS_AS 136
#define FS_BS 72
#define FINAL_SMEM ((64 * FS_AS + 2 * 64 * FS_BS + 64 * FS_AS + 256 + 128) * 4)
__global__ void __launch_bounds__(256) k_final(const float* __restrict__ xin,
                                               const float* __restrict__ ysum,
                                               const float* __restrict__ ipw,
                                               const float* __restrict__ lng,
                                               const float* __restrict__ lnb,
                                               const float* __restrict__ wo,
                                               float* __restrict__ out) {
    extern __shared__ float fs[];
    unsigned* As  = (unsigned*)fs;
    unsigned* Bwi = (unsigned*)(fs + 64 * FS_AS);
    unsigned* Bwo = Bwi + 64 * FS_BS;
    float* Gs     = fs + 64 * FS_AS + 2 * 64 * FS_BS;
    float* mus    = Gs + 64 * FS_AS;
    float* rss    = mus + 128;
    float* gsv    = rss + 128;
    float* bsv    = gsv + 64;
    int half = blockIdx.x, b = blockIdx.y;
    int t = threadIdx.x, w = t >> 5, lane = t & 31;
    int gid = lane >> 2, tig = lane & 3;
    int lbase = half * 128;

    for (int i = t; i < 4096; i += 256) {
        Bwi[(i & 63) * FS_BS + (i >> 6)] = f2tf(ipw[i]);
        Bwo[(i & 63) * FS_BS + (i >> 6)] = f2tf(wo[i]);
    }
    {
        int lr = t >> 1, kk0 = (t & 1) * 32;
        const float4* xp = (const float4*)(xin + (b * 256 + lbase + lr) * 64 + kk0);
#pragma unroll
        for (int j4 = 0; j4 < 8; j4++) {
            float4 v = __ldg(xp + j4);
            As[(kk0 + 4 * j4 + 0) * FS_AS + lr] = f2tf(v.x);
            As[(kk0 + 4 * j4 + 1) * FS_AS + lr] = f2tf(v.y);
            As[(kk0 + 4 * j4 + 2) * FS_AS + lr] = f2tf(v.z);
            As[(kk0 + 4 * j4 + 3) * FS_AS + lr] = f2tf(v.w);
        }
    }
    {
        const float* yb = ysum + (b * 256 + lbase) * 64;
#pragma unroll
        for (int i = 0; i < 32; i++) {
            int idx = i * 256 + t;
            Gs[(idx & 63) * FS_AS + (idx >> 6)] = yb[idx];
        }
    }
    if (t < 64) { gsv[t] = lng[t]; bsv[t] = lnb[t]; }
    __syncthreads();
    if (t < 128) {
        float s = 0.f;
#pragma unroll
        for (int e = 0; e < 64; e++) s += Gs[e * FS_AS + t];
        float mu = s * (1.f / 64.f);
        float v = 0.f;
#pragma unroll
        for (int e = 0; e < 64; e++) {
            float dd = Gs[e * FS_AS + t] - mu;
            v += dd * dd;
        }
        mus[t] = mu;
        rss[t] = rsqrtf(v * (1.f / 64.f) + 1e-5f);
    }
    __syncthreads();

    int r0 = w * 16;
    unsigned a[8][4];
#pragma unroll
    for (int ks = 0; ks < 8; ks++) {
        int kb = ks * 8;
        a[ks][0] = As[(kb + tig) * FS_AS + r0 + gid];
        a[ks][1] = As[(kb + tig) * FS_AS + r0 + gid + 8];
        a[ks][2] = As[(kb + tig + 4) * FS_AS + r0 + gid];
        a[ks][3] = As[(kb + tig + 4) * FS_AS + r0 + gid + 8];
    }
    unsigned* Gt = (unsigned*)Gs;
#pragma unroll
    for (int n = 0; n < 8; n++) {
        float acc[4] = {0.f, 0.f, 0.f, 0.f};
#pragma unroll
        for (int ks = 0; ks < 8; ks++) {
            int kb = ks * 8;
            unsigned b0 = Bwi[(kb + tig) * FS_BS + n * 8 + gid];
            unsigned b1 = Bwi[(kb + tig + 4) * FS_BS + n * 8 + gid];
            mma_tf32(acc, a[ks][0], a[ks][1], a[ks][2], a[ks][3], b0, b1);
        }
        int c0 = n * 8 + 2 * tig;
#pragma unroll
        for (int q = 0; q < 4; q++) {
            int c = c0 + (q & 1);
            int r = r0 + gid + ((q >> 1) * 8);
            float z = silu(acc[q]);
            float y = Gs[c * FS_AS + r];
            float g = ((y - mus[r]) * rss[r] * gsv[c] + bsv[c]) * z;
            Gt[c * FS_AS + r] = f2tf(g);
        }
    }
    __syncthreads();
#pragma unroll
    for (int ks = 0; ks < 8; ks++) {
        int kb = ks * 8;
        a[ks][0] = Gt[(kb + tig) * FS_AS + r0 + gid];
        a[ks][1] = Gt[(kb + tig) * FS_AS + r0 + gid + 8];
        a[ks][2] = Gt[(kb + tig + 4) * FS_AS + r0 + gid];
        a[ks][3] = Gt[(kb + tig + 4) * FS_AS + r0 + gid + 8];
    }
    float* ob = out + (b * 256 + lbase) * 64;
#pragma unroll
    for (int n = 0; n < 8; n++) {
        float acc[4] = {0.f, 0.f, 0.f, 0.f};
#pragma unroll
        for (int ks = 0; ks < 8; ks++) {
            int kb = ks * 8;
            unsigned b0 = Bwo[(kb + tig) * FS_BS + n * 8 + gid];
            unsigned b1 = Bwo[(kb + tig + 4) * FS_BS + n * 8 + gid];
            mma_tf32(acc, a[ks][0], a[ks][1], a[ks][2], a[ks][3], b0, b1);
        }
        int c0 = n * 8 + 2 * tig;
        int r = r0 + gid;
        *(float2*)&ob[r * 64 + c0]       = make_float2(acc[0], acc[1]);
        *(float2*)&ob[(r + 8) * 64 + c0] = make_float2(acc[2], acc[3]);
    }
}

// ---------------- launch ------------------------------------------------------
extern "C" void kernel_launch(void* const* d_in, const int* in_sizes, int n_in,
                              void* d_out, int out_size) {
    const float* x_in   = (const float*)d_in[0];
    const float* ipw    = (const float*)d_in[1];
    const float* conv_w = (const float*)d_in[2];
    const float* conv_b = (const float*)d_in[3];
    const float* patch_w= (const float*)d_in[4];
    const float* patch_b= (const float*)d_in[5];
    const float* bn_g   = (const float*)d_in[6];
    const float* bn_b   = (const float*)d_in[7];
    const float* bn_m   = (const float*)d_in[8];
    const float* bn_v   = (const float*)d_in[9];
    const float* xpw    = (const float*)d_in[10];
    const float* dtw    = (const float*)d_in[11];
    const float* dtb    = (const float*)d_in[12];
    const float* alog   = (const float*)d_in[13];
    const float* Dsv    = (const float*)d_in[14];
    const float* lng    = (const float*)d_in[15];
    const float* lnb    = (const float*)d_in[16];
    const float* wo     = (const float*)d_in[17];
    float* out = (float*)d_out;

    float *xt, *dtrg, *bcv, *ysum;
    cudaGetSymbolAddress((void**)&xt,   g_xt);
    cudaGetSymbolAddress((void**)&dtrg, g_dtr);
    cudaGetSymbolAddress((void**)&bcv,  g_bc);
    cudaGetSymbolAddress((void**)&ysum, g_ysum);

    cudaFuncSetAttribute(k_front, cudaFuncAttributeMaxDynamicSharedMemorySize,
                         FRONT_SMEM);
    cudaFuncSetAttribute(k_proj, cudaFuncAttributeMaxDynamicSharedMemorySize,
                         PROJ_SMEM);
    cudaFuncSetAttribute(k_final, cudaFuncAttributeMaxDynamicSharedMemorySize,
                         FINAL_SMEM);

    k_front<<<BATCH, 512, FRONT_SMEM>>>(x_in, conv_w, conv_b, patch_w, patch_b,
                                        bn_g, bn_b, bn_m, bn_v, xt, ysum);
    k_proj<<<dim3(8, BATCH), 256, PROJ_SMEM>>>(xt, xpw, dtrg, bcv);
    k_scan<<<dim3(4, BATCH), 64>>>(xt, dtrg, bcv, dtw, alog, dtb, Dsv, ysum);
    k_final<<<dim3(2, BATCH), 256, FINAL_SMEM>>>(x_in, ysum, ipw, lng, lnb, wo, out);
}